// round 1
// baseline (speedup 1.0000x reference)
#include <cuda_runtime.h>
#include <cuda_bf16.h>

#define N_NODES 50000
#define N_EDGES 800000
#define IN_DIM  128
#define OUT_DIM 64

// Scratch for xw = x @ W  (50000 x 64 fp32 = 12.8 MB). Static __device__ global
// per the no-allocation rules.
__device__ float g_xw[N_NODES * OUT_DIM];

// ---------------------------------------------------------------------------
// Zero the output buffer (it is poisoned to 0xAA before timing).
// ---------------------------------------------------------------------------
__global__ void __launch_bounds__(256) zero_kernel(float4* __restrict__ out4, int n4) {
    int i = blockIdx.x * blockDim.x + threadIdx.x;
    if (i < n4) out4[i] = make_float4(0.f, 0.f, 0.f, 0.f);
}

// ---------------------------------------------------------------------------
// GEMM: xw[r][c] = sum_k x[r][k] * W[k][c].  One warp per row.
// W (128x64 fp32 = 32 KB) staged in shared. Lane l owns output columns
// 2l and 2l+1 (contiguous float2), x row broadcast via shuffle.
// ---------------------------------------------------------------------------
__global__ void __launch_bounds__(256) gemm_kernel(const float* __restrict__ x,
                                                   const float* __restrict__ w) {
    __shared__ float ws[IN_DIM * OUT_DIM];  // [k][c] row-major
    for (int i = threadIdx.x; i < IN_DIM * OUT_DIM; i += blockDim.x)
        ws[i] = w[i];
    __syncthreads();

    const int lane   = threadIdx.x & 31;
    const int warp_g = (blockIdx.x * blockDim.x + threadIdx.x) >> 5;
    const int nwarp  = (gridDim.x * blockDim.x) >> 5;
    const float2* ws2 = reinterpret_cast<const float2*>(ws);

    for (int r = warp_g; r < N_NODES; r += nwarp) {
        // Each lane holds x[r][4*lane .. 4*lane+3]; warp covers the full row.
        float4 xv = reinterpret_cast<const float4*>(x + (size_t)r * IN_DIM)[lane];
        float acc0 = 0.f, acc1 = 0.f;
#pragma unroll
        for (int k = 0; k < IN_DIM; k++) {
            float comp;
            if      ((k & 3) == 0) comp = xv.x;
            else if ((k & 3) == 1) comp = xv.y;
            else if ((k & 3) == 2) comp = xv.z;
            else                   comp = xv.w;
            float xk = __shfl_sync(0xffffffffu, comp, k >> 2);
            float2 wv = ws2[k * 32 + lane];   // cols 2*lane, 2*lane+1
            acc0 = fmaf(xk, wv.x, acc0);
            acc1 = fmaf(xk, wv.y, acc1);
        }
        reinterpret_cast<float2*>(g_xw + (size_t)r * OUT_DIM)[lane] =
            make_float2(acc0, acc1);
    }
}

// ---------------------------------------------------------------------------
// COO SpMM scatter: out[row[e]] += val[e] * xw[col[e]].
// 16 threads per edge, one float4 (4 output columns) each.
// Vectorized fp32 atomics (sm_90+ atomicAdd(float4*)) -> 12.8M L2 REDs
// instead of 51.2M scalar ones. xw and out are L2-resident.
// ---------------------------------------------------------------------------
__global__ void __launch_bounds__(256) scatter_kernel(const int*   __restrict__ arow,
                                                      const int*   __restrict__ acol,
                                                      const float* __restrict__ aval,
                                                      float4*      __restrict__ out4) {
    int t = blockIdx.x * blockDim.x + threadIdx.x;
    int e = t >> 4;
    if (e >= N_EDGES) return;
    int q = t & 15;

    int   r = arow[e];
    int   c = acol[e];
    float v = aval[e];

    const float4* xw4 = reinterpret_cast<const float4*>(g_xw);
    float4 m = __ldg(&xw4[(size_t)c * 16 + q]);
    float4 add = make_float4(m.x * v, m.y * v, m.z * v, m.w * v);
    atomicAdd(&out4[(size_t)r * 16 + q], add);
}

// ---------------------------------------------------------------------------
// ReLU in place on the output.
// ---------------------------------------------------------------------------
__global__ void __launch_bounds__(256) relu_kernel(float4* __restrict__ out4, int n4) {
    int i = blockIdx.x * blockDim.x + threadIdx.x;
    if (i < n4) {
        float4 v = out4[i];
        v.x = fmaxf(v.x, 0.f);
        v.y = fmaxf(v.y, 0.f);
        v.z = fmaxf(v.z, 0.f);
        v.w = fmaxf(v.w, 0.f);
        out4[i] = v;
    }
}

extern "C" void kernel_launch(void* const* d_in, const int* in_sizes, int n_in,
                              void* d_out, int out_size) {
    const float* x    = (const float*)d_in[0];   // [50000, 128]
    const float* w    = (const float*)d_in[1];   // [128, 64]
    const int*   arow = (const int*)  d_in[2];   // [800000]
    const int*   acol = (const int*)  d_in[3];   // [800000]
    const float* aval = (const float*)d_in[4];   // [800000]
    float4* out4 = (float4*)d_out;               // [50000, 64] fp32

    const int n4 = N_NODES * OUT_DIM / 4;        // 800000 float4

    // 1) zero output (atomic accumulation target)
    zero_kernel<<<(n4 + 255) / 256, 256>>>(out4, n4);

    // 2) xw = x @ W   (one warp per row; 6250 blocks x 8 warps = 50000 warps)
    gemm_kernel<<<6250, 256>>>(x, w);

    // 3) edge scatter with float4 atomics (800000 edges * 16 threads)
    scatter_kernel<<<(N_EDGES * 16) / 256, 256>>>(arow, acol, aval, out4);

    // 4) ReLU in place
    relu_kernel<<<(n4 + 255) / 256, 256>>>(out4, n4);
}